// round 14
// baseline (speedup 1.0000x reference)
#include <cuda_runtime.h>
#include <cuda_fp16.h>
#include <math.h>
#include <stdint.h>

// Problem dims
constexpr int NB = 8, NT = 256, NU = 64, ND = 512, NH = 1024;
constexpr int PS_ROWS = NB * NT;              // 2048
constexpr int PT_ROWS = NB * NU;              // 512
constexpr int P_ROWS  = PS_ROWS + PT_ROWS;    // 2560
constexpr int M2      = NB * NT * NU;         // 131072
constexpr long MAIN_OUT = (long)M2 * ND;      // 67,108,864

// Scratch
__device__ float  g_P[(size_t)P_ROWS * NH];   // 10 MB
__device__ __half g_W1h[(size_t)NH * ND];     // W1^T [n][k] fp16 hi
__device__ __half g_W1l[(size_t)NH * ND];     // fp16 lo residual
__device__ __half g_W2h[(size_t)ND * NH];     // W2^T [n][k] fp16

// ===========================================================================
// Helpers (plain PTX, compute_100-safe)
// ===========================================================================
__device__ __forceinline__ uint32_t smem_u32(const void* p) {
    uint32_t a;
    asm("{ .reg .u64 t; cvta.to.shared.u64 t, %1; cvt.u32.u64 %0, t; }" : "=r"(a) : "l"(p));
    return a;
}

#define LDSM_X4(r, addr) \
    asm volatile("ldmatrix.sync.aligned.m8n8.x4.shared.b16 {%0,%1,%2,%3}, [%4];" \
        : "=r"((r)[0]), "=r"((r)[1]), "=r"((r)[2]), "=r"((r)[3]) : "r"(addr))

__device__ __forceinline__ void mma16816(float* d, const uint32_t* a,
                                         uint32_t b0, uint32_t b1) {
    asm volatile(
        "mma.sync.aligned.m16n8k16.row.col.f32.f16.f16.f32 "
        "{%0,%1,%2,%3}, {%4,%5,%6,%7}, {%8,%9}, {%0,%1,%2,%3};"
        : "+f"(d[0]), "+f"(d[1]), "+f"(d[2]), "+f"(d[3])
        : "r"(a[0]), "r"(a[1]), "r"(a[2]), "r"(a[3]), "r"(b0), "r"(b1));
}

__device__ __forceinline__ void cp_async16(uint32_t dst, const void* src) {
    asm volatile("cp.async.cg.shared.global [%0], [%1], 16;"
        :: "r"(dst), "l"(__cvta_generic_to_global(src)) : "memory");
}
#define CP_COMMIT()  asm volatile("cp.async.commit_group;" ::: "memory")
#define CP_WAIT(n)   asm volatile("cp.async.wait_group %0;" :: "n"(n) : "memory")

// HW tanh (sm_75+): 1 MUFU op; error below fp16 quantization (measured R12).
__device__ __forceinline__ float hw_tanh(float x) {
    float y;
    asm("tanh.approx.f32 %0, %1;" : "=f"(y) : "f"(x));
    return y;
}

// ===========================================================================
// Weight preconverts (fused single kernel)
// ===========================================================================
constexpr int W1N = NH * ND;                  // 524288
constexpr int W2N = ND * NH;                  // 524288
__global__ __launch_bounds__(256) void wconv_kernel(
    const float* __restrict__ W1, const float* __restrict__ W2)
{
    int i = blockIdx.x * 256 + threadIdx.x;
    if (i < W1N) {                            // [n][k], n<NH, k<ND
        int n = i >> 9;
        int k = i & (ND - 1);
        float v = W1[(size_t)k * NH + n];
        __half h = __float2half_rn(v);
        g_W1h[i] = h;
        g_W1l[i] = __float2half_rn(v - __half2float(h));
    } else {                                  // [n][k], n<ND, k<NH
        int j = i - W1N;
        int n = j >> 10;
        int k = j & (NH - 1);
        g_W2h[j] = __float2half_rn(W2[(size_t)k * ND + n]);
    }
}

// ===========================================================================
// Stage 1 (mma.sync, 3-product fp16 split): P = concat(S,Tgt) @ W1 (+b1 Tgt)
// ===========================================================================
constexpr int RS1     = 80;
constexpr int KCH1    = 32;
constexpr int NCH1    = ND / KCH1;            // 16
constexpr int TILE1   = 128 * RS1;            // 10240
constexpr int BUFSZ1  = 4 * TILE1;            // Ah, Al, Bh, Bl
constexpr int SMEM1   = 2 * BUFSZ1;           // 81920

__global__ void __launch_bounds__(256, 2) stage1_mma_kernel(
    const float* __restrict__ src, const float* __restrict__ tgt,
    const float* __restrict__ b1)
{
    extern __shared__ __align__(16) unsigned char dynsm[];

    const int tid  = threadIdx.x;
    const int lane = tid & 31, wid = tid >> 5;
    const int warpM = wid >> 1, warpN = wid & 1;
    const int nBase = blockIdx.x * 128;
    const int mBase = blockIdx.y * 128;
    const bool isTgt = (mBase >= PS_ROWS);

    const int gr = tid >> 1;
    const int gk = (tid & 1) * 16;
    const float* aRow = (isTgt ? tgt + (size_t)(mBase - PS_ROWS + gr) * ND
                               : src + (size_t)(mBase + gr) * ND) + gk;
    const __half* bhS = g_W1h + (size_t)(nBase + gr) * ND + gk;
    const __half* blS = g_W1l + (size_t)(nBase + gr) * ND + gk;

    const int sel = lane >> 3, l7 = lane & 7;
    const uint32_t aOff = (uint32_t)((warpM * 32 + (sel & 1) * 8 + l7) * RS1 + (sel >> 1) * 16);
    const uint32_t bOff = (uint32_t)((warpN * 64 + ((sel >> 1) & 1) * 8 + l7) * RS1 + (sel & 1) * 16);
    const uint32_t sbase = smem_u32(dynsm);

    float acc[2][8][4];
    #pragma unroll
    for (int mt = 0; mt < 2; ++mt)
        #pragma unroll
        for (int nt = 0; nt < 8; ++nt)
            #pragma unroll
            for (int j = 0; j < 4; ++j) acc[mt][nt][j] = 0.f;

    auto gen = [&](int c, int buf) {
        unsigned char* bp = dynsm + buf * BUFSZ1;
        const float* p = aRow + c * KCH1;
        uint32_t hw[8], lw[8];
        #pragma unroll
        for (int g = 0; g < 4; ++g) {
            float4 p4 = *(const float4*)(p + g * 4);
            __half hx = __float2half_rn(p4.x), hy = __float2half_rn(p4.y);
            __half hz = __float2half_rn(p4.z), hw4 = __float2half_rn(p4.w);
            __half2 h0; h0.x = hx; h0.y = hy;
            __half2 h1; h1.x = hz; h1.y = hw4;
            __half2 l0 = __floats2half2_rn(p4.x - __half2float(hx), p4.y - __half2float(hy));
            __half2 l1 = __floats2half2_rn(p4.z - __half2float(hz), p4.w - __half2float(hw4));
            hw[g * 2 + 0] = *(uint32_t*)&h0; hw[g * 2 + 1] = *(uint32_t*)&h1;
            lw[g * 2 + 0] = *(uint32_t*)&l0; lw[g * 2 + 1] = *(uint32_t*)&l1;
        }
        unsigned char* aH = bp + gr * RS1 + gk * 2;
        unsigned char* aL = aH + TILE1;
        *(uint4*)(aH)      = make_uint4(hw[0], hw[1], hw[2], hw[3]);
        *(uint4*)(aH + 16) = make_uint4(hw[4], hw[5], hw[6], hw[7]);
        *(uint4*)(aL)      = make_uint4(lw[0], lw[1], lw[2], lw[3]);
        *(uint4*)(aL + 16) = make_uint4(lw[4], lw[5], lw[6], lw[7]);

        uint4 h0 = *(const uint4*)(bhS + c * KCH1);
        uint4 h1 = *(const uint4*)(bhS + c * KCH1 + 8);
        uint4 l0 = *(const uint4*)(blS + c * KCH1);
        uint4 l1 = *(const uint4*)(blS + c * KCH1 + 8);
        unsigned char* bH = bp + 2 * TILE1 + gr * RS1 + gk * 2;
        unsigned char* bL = bH + TILE1;
        *(uint4*)(bH)      = h0; *(uint4*)(bH + 16) = h1;
        *(uint4*)(bL)      = l0; *(uint4*)(bL + 16) = l1;
    };

    gen(0, 0);
    __syncthreads();

    for (int c = 0; c < NCH1; ++c) {
        const int buf = c & 1;
        const uint32_t base = sbase + buf * BUFSZ1;

        uint32_t ah[2][2][4], al[2][2][4];
        #pragma unroll
        for (int ks = 0; ks < 2; ++ks) {
            LDSM_X4(ah[ks][0], base + aOff + ks * 32);
            LDSM_X4(ah[ks][1], base + aOff + 16 * RS1 + ks * 32);
            LDSM_X4(al[ks][0], base + TILE1 + aOff + ks * 32);
            LDSM_X4(al[ks][1], base + TILE1 + aOff + 16 * RS1 + ks * 32);
        }
        #pragma unroll
        for (int pass = 0; pass < 3; ++pass) {
            const uint32_t bB = base + (pass == 1 ? 3 : 2) * TILE1 + bOff;
            #pragma unroll
            for (int ks = 0; ks < 2; ++ks) {
                uint32_t bf[4][4];
                #pragma unroll
                for (int g = 0; g < 4; ++g)
                    LDSM_X4(bf[g], bB + g * 16 * RS1 + ks * 32);
                #pragma unroll
                for (int mt = 0; mt < 2; ++mt)
                    #pragma unroll
                    for (int nt = 0; nt < 8; ++nt)
                        mma16816(acc[mt][nt],
                                 (pass == 2 ? al[ks][mt] : ah[ks][mt]),
                                 bf[nt >> 1][(nt & 1) * 2 + 0],
                                 bf[nt >> 1][(nt & 1) * 2 + 1]);
            }
        }
        if (c + 1 < NCH1) gen(c + 1, buf ^ 1);
        __syncthreads();
    }

    const int colOff = (lane & 3) * 2;
    const int rowOff = lane >> 2;
    #pragma unroll
    for (int mt = 0; mt < 2; ++mt) {
        const int r0 = mBase + warpM * 32 + mt * 16 + rowOff;
        float* row0 = g_P + (size_t)r0 * NH + nBase + warpN * 64 + colOff;
        float* row1 = row0 + (size_t)8 * NH;
        #pragma unroll
        for (int nt = 0; nt < 8; ++nt) {
            const int col = nBase + warpN * 64 + nt * 8 + colOff;
            const float bx = isTgt ? __ldg(b1 + col)     : 0.f;
            const float by = isTgt ? __ldg(b1 + col + 1) : 0.f;
            *(float2*)(row0 + nt * 8) = make_float2(acc[mt][nt][0] + bx, acc[mt][nt][1] + by);
            *(float2*)(row1 + nt * 8) = make_float2(acc[mt][nt][2] + bx, acc[mt][nt][3] + by);
        }
    }
}

// ===========================================================================
// Stage 2 (fused): out = tanh(Ps+Pt) @ W2^T + b2
//   A generated in-kernel (hw_tanh -> fp16, smem double buffer);
//   B via 3-stage cp.async. k-chunk 32, RS 80 (R13-validated layout).
//   SMEM: [B stage0][B stage1][B stage2][A buf0][A buf1] = 5 * 10240.
// ===========================================================================
constexpr int RS2  = 80;
constexpr int KCH2 = 32;
constexpr int NCH2 = NH / KCH2;               // 32
constexpr int TILE2  = 128 * RS2;             // 10240
constexpr int NSTAGE = 3;
constexpr int SMEM2  = (NSTAGE + 2) * TILE2;  // 51200

__global__ void __launch_bounds__(256, 2) stage2_fused_kernel(
    const float* __restrict__ b2, float* __restrict__ out)
{
    extern __shared__ __align__(16) unsigned char dynsm[];

    const int tid  = threadIdx.x;
    const int lane = tid & 31, wid = tid >> 5;
    const int warpM = wid >> 1, warpN = wid & 1;
    const int nBase = blockIdx.x * 128;
    const int mBase = blockIdx.y * 128;

    // gen/copy mapping: row = tid>>1, k-half = (tid&1)*16
    const int gr = tid >> 1;
    const int gk = (tid & 1) * 16;
    const int mG = mBase + gr;
    const int bb = mG >> 14;
    const int tt = (mG >> 6) & (NT - 1);
    const int uu = mG & (NU - 1);
    const float* ps = g_P + (size_t)(bb * NT + tt) * NH + gk;
    const float* pt = g_P + (size_t)(PS_ROWS + bb * NU + uu) * NH + gk;
    const __half* bS0 = g_W2h + (size_t)(nBase + gr) * NH + gk;
    const uint32_t dOffB = (uint32_t)(gr * RS2 + gk * 2);

    const int sel = lane >> 3, l7 = lane & 7;
    const uint32_t aOff = (uint32_t)((warpM * 32 + (sel & 1) * 8 + l7) * RS2 + (sel >> 1) * 16);
    const uint32_t bOff = (uint32_t)((warpN * 64 + ((sel >> 1) & 1) * 8 + l7) * RS2 + (sel & 1) * 16);
    const uint32_t sbase = smem_u32(dynsm);
    const uint32_t aRegion = sbase + NSTAGE * TILE2;

    float acc[2][8][4];
    #pragma unroll
    for (int mt = 0; mt < 2; ++mt)
        #pragma unroll
        for (int nt = 0; nt < 8; ++nt)
            #pragma unroll
            for (int j = 0; j < 4; ++j) acc[mt][nt][j] = 0.f;

    auto issue_cpB = [&](int c, int stage) {
        const uint32_t dst = sbase + stage * TILE2 + dOffB;
        const __half* bS = bS0 + c * KCH2;
        cp_async16(dst,      bS);
        cp_async16(dst + 16, bS + 8);
        CP_COMMIT();
    };

    // Generate A chunk c (tanh.approx -> fp16) into A buffer buf.
    auto genA = [&](int c, int buf) {
        const float* p = ps + c * KCH2;
        const float* q = pt + c * KCH2;
        uint32_t hw[8];
        #pragma unroll
        for (int g = 0; g < 4; ++g) {
            float4 p4 = *(const float4*)(p + g * 4);
            float4 q4 = *(const float4*)(q + g * 4);
            __half2 h0 = __floats2half2_rn(hw_tanh(p4.x + q4.x), hw_tanh(p4.y + q4.y));
            __half2 h1 = __floats2half2_rn(hw_tanh(p4.z + q4.z), hw_tanh(p4.w + q4.w));
            hw[g * 2 + 0] = *(uint32_t*)&h0;
            hw[g * 2 + 1] = *(uint32_t*)&h1;
        }
        unsigned char* aD = dynsm + (NSTAGE + buf) * TILE2 + gr * RS2 + gk * 2;
        *(uint4*)(aD)      = make_uint4(hw[0], hw[1], hw[2], hw[3]);
        *(uint4*)(aD + 16) = make_uint4(hw[4], hw[5], hw[6], hw[7]);
    };

    genA(0, 0);
    issue_cpB(0, 0);
    issue_cpB(1, 1);

    int rd = 0, wr = 2;
    for (int c = 0; c < NCH2; ++c) {
        if (c == NCH2 - 1) { CP_WAIT(0); } else { CP_WAIT(1); }
        __syncthreads();          // B(c) visible; A(c) gen from prev iter visible

        const uint32_t aB = aRegion + (c & 1) * TILE2 + aOff;
        const uint32_t bB = sbase + rd * TILE2 + bOff;

        #pragma unroll
        for (int ks = 0; ks < 2; ++ks) {
            uint32_t a[2][4];
            LDSM_X4(a[0], aB + ks * 32);
            LDSM_X4(a[1], aB + 16 * RS2 + ks * 32);
            uint32_t bf[4][4];
            #pragma unroll
            for (int g = 0; g < 4; ++g)
                LDSM_X4(bf[g], bB + g * 16 * RS2 + ks * 32);
            #pragma unroll
            for (int mt = 0; mt < 2; ++mt)
                #pragma unroll
                for (int nt = 0; nt < 8; ++nt)
                    mma16816(acc[mt][nt], a[mt],
                             bf[nt >> 1][(nt & 1) * 2 + 0],
                             bf[nt >> 1][(nt & 1) * 2 + 1]);
        }

        if (c + 2 < NCH2) issue_cpB(c + 2, wr);
        if (c + 1 < NCH2) genA(c + 1, (c + 1) & 1);   // opposite A buffer
        rd = (rd == 2) ? 0 : rd + 1;
        wr = (wr == 2) ? 0 : wr + 1;
    }

    // Epilogue: + b2, direct stores
    const int colOff = (lane & 3) * 2;
    const int rowOff = lane >> 2;
    #pragma unroll
    for (int mt = 0; mt < 2; ++mt) {
        const int r0 = mBase + warpM * 32 + mt * 16 + rowOff;
        float* row0 = out + (size_t)r0 * ND + nBase + warpN * 64 + colOff;
        float* row1 = row0 + (size_t)8 * ND;
        #pragma unroll
        for (int nt = 0; nt < 8; ++nt) {
            const float bx = __ldg(b2 + nBase + warpN * 64 + nt * 8 + colOff);
            const float by = __ldg(b2 + nBase + warpN * 64 + nt * 8 + colOff + 1);
            *(float2*)(row0 + nt * 8) = make_float2(acc[mt][nt][0] + bx, acc[mt][nt][1] + by);
            *(float2*)(row1 + nt * 8) = make_float2(acc[mt][nt][2] + bx, acc[mt][nt][3] + by);
        }
    }
}

// ---------------------------------------------------------------------------
// Length pass-through tail
// ---------------------------------------------------------------------------
__global__ void tail_kernel(const int* __restrict__ sl, const int* __restrict__ tl,
                            float* __restrict__ out)
{
    const int i = threadIdx.x;
    if (i < NB)           out[MAIN_OUT + i] = (float)sl[i];
    else if (i < 2 * NB)  out[MAIN_OUT + i] = (float)tl[i - NB];
}

extern "C" void kernel_launch(void* const* d_in, const int* in_sizes, int n_in,
                              void* d_out, int out_size)
{
    const float* src  = (const float*)d_in[0];
    const int*   slen = (const int*)  d_in[1];
    const float* tgt  = (const float*)d_in[2];
    const int*   tlen = (const int*)  d_in[3];
    const float* W1   = (const float*)d_in[4];
    const float* b1   = (const float*)d_in[5];
    const float* W2   = (const float*)d_in[6];
    const float* b2   = (const float*)d_in[7];
    float* out = (float*)d_out;

    // Opt-in to >48KB dynamic smem (host-side, capture-safe).
    cudaFuncSetAttribute(stage1_mma_kernel,
                         cudaFuncAttributeMaxDynamicSharedMemorySize, SMEM1);
    cudaFuncSetAttribute(stage2_fused_kernel,
                         cudaFuncAttributeMaxDynamicSharedMemorySize, SMEM2);

    // Fused weight preconverts
    wconv_kernel<<<(W1N + W2N) / 256, 256>>>(W1, W2);

    // Stage 1: P = [S; Tgt] @ W1 (+ b1 on Tgt rows)
    stage1_mma_kernel<<<dim3(NH / 128, P_ROWS / 128), 256, SMEM1>>>(src, tgt, b1);

    // Stage 2 (fused): out = tanh(Ps+Pt) @ W2 + b2, A generated in-kernel
    stage2_fused_kernel<<<dim3(ND / 128, M2 / 128), 256, SMEM2>>>(b2, out);

    // Length pass-through if the output buffer has room
    if ((long)out_size >= MAIN_OUT + 2 * NB)
        tail_kernel<<<1, 32>>>(slen, tlen, out);
}

// round 15
// speedup vs baseline: 1.2961x; 1.2961x over previous
#include <cuda_runtime.h>
#include <cuda_fp16.h>
#include <math.h>
#include <stdint.h>

// Problem dims
constexpr int NB = 8, NT = 256, NU = 64, ND = 512, NH = 1024;
constexpr int PS_ROWS = NB * NT;              // 2048
constexpr int PT_ROWS = NB * NU;              // 512
constexpr int P_ROWS  = PS_ROWS + PT_ROWS;    // 2560
constexpr int M2      = NB * NT * NU;         // 131072
constexpr long MAIN_OUT = (long)M2 * ND;      // 67,108,864

// Scratch
__device__ float  g_P[(size_t)P_ROWS * NH];   // 10 MB
__device__ __half g_W1h[(size_t)NH * ND];     // W1^T [n][k] fp16 hi
__device__ __half g_W1l[(size_t)NH * ND];     // fp16 lo residual
__device__ __half g_W2h[(size_t)ND * NH];     // W2^T [n][k] fp16
__device__ __half g_H[(size_t)M2 * NH];       // H = fp16(tanh(Ps+Pt)), 268 MB

// ===========================================================================
// Helpers (plain PTX, compute_100-safe)
// ===========================================================================
__device__ __forceinline__ uint32_t smem_u32(const void* p) {
    uint32_t a;
    asm("{ .reg .u64 t; cvta.to.shared.u64 t, %1; cvt.u32.u64 %0, t; }" : "=r"(a) : "l"(p));
    return a;
}

#define LDSM_X4(r, addr) \
    asm volatile("ldmatrix.sync.aligned.m8n8.x4.shared.b16 {%0,%1,%2,%3}, [%4];" \
        : "=r"((r)[0]), "=r"((r)[1]), "=r"((r)[2]), "=r"((r)[3]) : "r"(addr))

__device__ __forceinline__ void mma16816(float* d, const uint32_t* a,
                                         uint32_t b0, uint32_t b1) {
    asm volatile(
        "mma.sync.aligned.m16n8k16.row.col.f32.f16.f16.f32 "
        "{%0,%1,%2,%3}, {%4,%5,%6,%7}, {%8,%9}, {%0,%1,%2,%3};"
        : "+f"(d[0]), "+f"(d[1]), "+f"(d[2]), "+f"(d[3])
        : "r"(a[0]), "r"(a[1]), "r"(a[2]), "r"(a[3]), "r"(b0), "r"(b1));
}

__device__ __forceinline__ void cp_async16(uint32_t dst, const void* src) {
    asm volatile("cp.async.cg.shared.global [%0], [%1], 16;"
        :: "r"(dst), "l"(__cvta_generic_to_global(src)) : "memory");
}
#define CP_COMMIT()  asm volatile("cp.async.commit_group;" ::: "memory")
#define CP_WAIT(n)   asm volatile("cp.async.wait_group %0;" :: "n"(n) : "memory")

// HW tanh (sm_75+): 1 MUFU op; error below fp16 quantization (measured R12).
__device__ __forceinline__ float hw_tanh(float x) {
    float y;
    asm("tanh.approx.f32 %0, %1;" : "=f"(y) : "f"(x));
    return y;
}

// ===========================================================================
// Weight preconverts (fused single kernel)
// ===========================================================================
constexpr int W1N = NH * ND;                  // 524288
constexpr int W2N = ND * NH;                  // 524288
__global__ __launch_bounds__(256) void wconv_kernel(
    const float* __restrict__ W1, const float* __restrict__ W2)
{
    int i = blockIdx.x * 256 + threadIdx.x;
    if (i < W1N) {                            // [n][k], n<NH, k<ND
        int n = i >> 9;
        int k = i & (ND - 1);
        float v = W1[(size_t)k * NH + n];
        __half h = __float2half_rn(v);
        g_W1h[i] = h;
        g_W1l[i] = __float2half_rn(v - __half2float(h));
    } else {                                  // [n][k], n<ND, k<NH
        int j = i - W1N;
        int n = j >> 10;
        int k = j & (NH - 1);
        g_W2h[j] = __float2half_rn(W2[(size_t)k * ND + n]);
    }
}

// ===========================================================================
// Stage 1 (mma.sync, 3-product fp16 split): P = concat(S,Tgt) @ W1 (+b1 Tgt)
// ===========================================================================
constexpr int RS1     = 80;
constexpr int KCH1    = 32;
constexpr int NCH1    = ND / KCH1;            // 16
constexpr int TILE1   = 128 * RS1;            // 10240
constexpr int BUFSZ1  = 4 * TILE1;            // Ah, Al, Bh, Bl
constexpr int SMEM1   = 2 * BUFSZ1;           // 81920

__global__ void __launch_bounds__(256, 2) stage1_mma_kernel(
    const float* __restrict__ src, const float* __restrict__ tgt,
    const float* __restrict__ b1)
{
    extern __shared__ __align__(16) unsigned char dynsm[];

    const int tid  = threadIdx.x;
    const int lane = tid & 31, wid = tid >> 5;
    const int warpM = wid >> 1, warpN = wid & 1;
    const int nBase = blockIdx.x * 128;
    const int mBase = blockIdx.y * 128;
    const bool isTgt = (mBase >= PS_ROWS);

    const int gr = tid >> 1;
    const int gk = (tid & 1) * 16;
    const float* aRow = (isTgt ? tgt + (size_t)(mBase - PS_ROWS + gr) * ND
                               : src + (size_t)(mBase + gr) * ND) + gk;
    const __half* bhS = g_W1h + (size_t)(nBase + gr) * ND + gk;
    const __half* blS = g_W1l + (size_t)(nBase + gr) * ND + gk;

    const int sel = lane >> 3, l7 = lane & 7;
    const uint32_t aOff = (uint32_t)((warpM * 32 + (sel & 1) * 8 + l7) * RS1 + (sel >> 1) * 16);
    const uint32_t bOff = (uint32_t)((warpN * 64 + ((sel >> 1) & 1) * 8 + l7) * RS1 + (sel & 1) * 16);
    const uint32_t sbase = smem_u32(dynsm);

    float acc[2][8][4];
    #pragma unroll
    for (int mt = 0; mt < 2; ++mt)
        #pragma unroll
        for (int nt = 0; nt < 8; ++nt)
            #pragma unroll
            for (int j = 0; j < 4; ++j) acc[mt][nt][j] = 0.f;

    auto gen = [&](int c, int buf) {
        unsigned char* bp = dynsm + buf * BUFSZ1;
        const float* p = aRow + c * KCH1;
        uint32_t hw[8], lw[8];
        #pragma unroll
        for (int g = 0; g < 4; ++g) {
            float4 p4 = *(const float4*)(p + g * 4);
            __half hx = __float2half_rn(p4.x), hy = __float2half_rn(p4.y);
            __half hz = __float2half_rn(p4.z), hw4 = __float2half_rn(p4.w);
            __half2 h0; h0.x = hx; h0.y = hy;
            __half2 h1; h1.x = hz; h1.y = hw4;
            __half2 l0 = __floats2half2_rn(p4.x - __half2float(hx), p4.y - __half2float(hy));
            __half2 l1 = __floats2half2_rn(p4.z - __half2float(hz), p4.w - __half2float(hw4));
            hw[g * 2 + 0] = *(uint32_t*)&h0; hw[g * 2 + 1] = *(uint32_t*)&h1;
            lw[g * 2 + 0] = *(uint32_t*)&l0; lw[g * 2 + 1] = *(uint32_t*)&l1;
        }
        unsigned char* aH = bp + gr * RS1 + gk * 2;
        unsigned char* aL = aH + TILE1;
        *(uint4*)(aH)      = make_uint4(hw[0], hw[1], hw[2], hw[3]);
        *(uint4*)(aH + 16) = make_uint4(hw[4], hw[5], hw[6], hw[7]);
        *(uint4*)(aL)      = make_uint4(lw[0], lw[1], lw[2], lw[3]);
        *(uint4*)(aL + 16) = make_uint4(lw[4], lw[5], lw[6], lw[7]);

        uint4 h0 = *(const uint4*)(bhS + c * KCH1);
        uint4 h1 = *(const uint4*)(bhS + c * KCH1 + 8);
        uint4 l0 = *(const uint4*)(blS + c * KCH1);
        uint4 l1 = *(const uint4*)(blS + c * KCH1 + 8);
        unsigned char* bH = bp + 2 * TILE1 + gr * RS1 + gk * 2;
        unsigned char* bL = bH + TILE1;
        *(uint4*)(bH)      = h0; *(uint4*)(bH + 16) = h1;
        *(uint4*)(bL)      = l0; *(uint4*)(bL + 16) = l1;
    };

    gen(0, 0);
    __syncthreads();

    for (int c = 0; c < NCH1; ++c) {
        const int buf = c & 1;
        const uint32_t base = sbase + buf * BUFSZ1;

        uint32_t ah[2][2][4], al[2][2][4];
        #pragma unroll
        for (int ks = 0; ks < 2; ++ks) {
            LDSM_X4(ah[ks][0], base + aOff + ks * 32);
            LDSM_X4(ah[ks][1], base + aOff + 16 * RS1 + ks * 32);
            LDSM_X4(al[ks][0], base + TILE1 + aOff + ks * 32);
            LDSM_X4(al[ks][1], base + TILE1 + aOff + 16 * RS1 + ks * 32);
        }
        #pragma unroll
        for (int pass = 0; pass < 3; ++pass) {
            const uint32_t bB = base + (pass == 1 ? 3 : 2) * TILE1 + bOff;
            #pragma unroll
            for (int ks = 0; ks < 2; ++ks) {
                uint32_t bf[4][4];
                #pragma unroll
                for (int g = 0; g < 4; ++g)
                    LDSM_X4(bf[g], bB + g * 16 * RS1 + ks * 32);
                #pragma unroll
                for (int mt = 0; mt < 2; ++mt)
                    #pragma unroll
                    for (int nt = 0; nt < 8; ++nt)
                        mma16816(acc[mt][nt],
                                 (pass == 2 ? al[ks][mt] : ah[ks][mt]),
                                 bf[nt >> 1][(nt & 1) * 2 + 0],
                                 bf[nt >> 1][(nt & 1) * 2 + 1]);
            }
        }
        if (c + 1 < NCH1) gen(c + 1, buf ^ 1);
        __syncthreads();
    }

    const int colOff = (lane & 3) * 2;
    const int rowOff = lane >> 2;
    #pragma unroll
    for (int mt = 0; mt < 2; ++mt) {
        const int r0 = mBase + warpM * 32 + mt * 16 + rowOff;
        float* row0 = g_P + (size_t)r0 * NH + nBase + warpN * 64 + colOff;
        float* row1 = row0 + (size_t)8 * NH;
        #pragma unroll
        for (int nt = 0; nt < 8; ++nt) {
            const int col = nBase + warpN * 64 + nt * 8 + colOff;
            const float bx = isTgt ? __ldg(b1 + col)     : 0.f;
            const float by = isTgt ? __ldg(b1 + col + 1) : 0.f;
            *(float2*)(row0 + nt * 8) = make_float2(acc[mt][nt][0] + bx, acc[mt][nt][1] + by);
            *(float2*)(row1 + nt * 8) = make_float2(acc[mt][nt][2] + bx, acc[mt][nt][3] + by);
        }
    }
}

// ===========================================================================
// Stage 1.5: H[m][k] = fp16(tanh.approx(Ps[b,t][k] + Pt[b,u][k]))
//   256 threads/block: two u-halves of 32 each -> 2x parallelism vs R13,
//   same addresses and bit-identical values.
// ===========================================================================
__global__ __launch_bounds__(256) void h_kernel()
{
    const int bt   = blockIdx.x;              // b*NT + t
    const int b    = bt >> 8;
    const int half = threadIdx.x >> 7;        // 0 or 1
    const int k0   = (threadIdx.x & 127) * 8;

    const float* ps = g_P + (size_t)bt * NH + k0;
    const float4 p0 = *(const float4*)(ps);
    const float4 p1 = *(const float4*)(ps + 4);

    const int u0 = half * 32;
    const float* ptB = g_P + (size_t)(PS_ROWS + b * NU + u0) * NH + k0;
    __half* hout = g_H + (size_t)(bt * NU + u0) * NH + k0;

    for (int u = 0; u < 32; ++u) {
        const float* q = ptB + (size_t)u * NH;
        float4 q0 = *(const float4*)(q);
        float4 q1 = *(const float4*)(q + 4);
        __half2 h0 = __floats2half2_rn(hw_tanh(p0.x + q0.x), hw_tanh(p0.y + q0.y));
        __half2 h1 = __floats2half2_rn(hw_tanh(p0.z + q0.z), hw_tanh(p0.w + q0.w));
        __half2 h2 = __floats2half2_rn(hw_tanh(p1.x + q1.x), hw_tanh(p1.y + q1.y));
        __half2 h3 = __floats2half2_rn(hw_tanh(p1.z + q1.z), hw_tanh(p1.w + q1.w));
        *(uint4*)(hout + (size_t)u * NH) =
            make_uint4(*(uint32_t*)&h0, *(uint32_t*)&h1, *(uint32_t*)&h2, *(uint32_t*)&h3);
    }
}

// ===========================================================================
// Stage 2: out = H @ W2^T + b2 — fp16 GEMM, R13-exact config:
//   k-chunk 32, RS 80, 3-stage cp.async.
// ===========================================================================
constexpr int RS2  = 80;                      // bytes per 32-fp16 row (padded)
constexpr int KCH2 = 32;
constexpr int NCH2 = NH / KCH2;               // 32
constexpr int TILE2  = 128 * RS2;             // 10240
constexpr int BUFSZ2 = 2 * TILE2;             // A, B
constexpr int NSTAGE = 3;
constexpr int SMEM2  = NSTAGE * BUFSZ2;       // 61440

__global__ void __launch_bounds__(256, 2) stage2_mma_kernel(
    const float* __restrict__ b2, float* __restrict__ out)
{
    extern __shared__ __align__(16) unsigned char dynsm[];

    const int tid  = threadIdx.x;
    const int lane = tid & 31, wid = tid >> 5;
    const int warpM = wid >> 1, warpN = wid & 1;
    const int nBase = blockIdx.x * 128;
    const int mBase = blockIdx.y * 128;

    // copy mapping: row = tid>>1, k-half = (tid&1)*16
    const int gr = tid >> 1;
    const int gk = (tid & 1) * 16;
    const __half* aS0 = g_H   + (size_t)(mBase + gr) * NH + gk;
    const __half* bS0 = g_W2h + (size_t)(nBase + gr) * NH + gk;
    const uint32_t dOffA = (uint32_t)(gr * RS2 + gk * 2);
    const uint32_t dOffB = (uint32_t)(TILE2 + gr * RS2 + gk * 2);

    const int sel = lane >> 3, l7 = lane & 7;
    const uint32_t aOff = (uint32_t)((warpM * 32 + (sel & 1) * 8 + l7) * RS2 + (sel >> 1) * 16);
    const uint32_t bOff = (uint32_t)((warpN * 64 + ((sel >> 1) & 1) * 8 + l7) * RS2 + (sel & 1) * 16);
    const uint32_t sbase = smem_u32(dynsm);

    float acc[2][8][4];
    #pragma unroll
    for (int mt = 0; mt < 2; ++mt)
        #pragma unroll
        for (int nt = 0; nt < 8; ++nt)
            #pragma unroll
            for (int j = 0; j < 4; ++j) acc[mt][nt][j] = 0.f;

    auto issue_cp = [&](int c, int stage) {
        const uint32_t base = sbase + stage * BUFSZ2;
        const __half* aS = aS0 + c * KCH2;
        const __half* bS = bS0 + c * KCH2;
        cp_async16(base + dOffA,      aS);
        cp_async16(base + dOffA + 16, aS + 8);
        cp_async16(base + dOffB,      bS);
        cp_async16(base + dOffB + 16, bS + 8);
        CP_COMMIT();
    };

    issue_cp(0, 0);
    issue_cp(1, 1);

    int rd = 0, wr = 2;
    for (int c = 0; c < NCH2; ++c) {
        if (c == NCH2 - 1) { CP_WAIT(0); } else { CP_WAIT(1); }
        __syncthreads();

        const uint32_t base = sbase + rd * BUFSZ2;
        const uint32_t aB = base + aOff;
        const uint32_t bB = base + TILE2 + bOff;

        #pragma unroll
        for (int ks = 0; ks < 2; ++ks) {
            uint32_t a[2][4];
            LDSM_X4(a[0], aB + ks * 32);
            LDSM_X4(a[1], aB + 16 * RS2 + ks * 32);
            uint32_t bf[4][4];
            #pragma unroll
            for (int g = 0; g < 4; ++g)
                LDSM_X4(bf[g], bB + g * 16 * RS2 + ks * 32);
            #pragma unroll
            for (int mt = 0; mt < 2; ++mt)
                #pragma unroll
                for (int nt = 0; nt < 8; ++nt)
                    mma16816(acc[mt][nt], a[mt],
                             bf[nt >> 1][(nt & 1) * 2 + 0],
                             bf[nt >> 1][(nt & 1) * 2 + 1]);
        }

        if (c + 2 < NCH2) issue_cp(c + 2, wr);
        rd = (rd == 2) ? 0 : rd + 1;
        wr = (wr == 2) ? 0 : wr + 1;
    }

    // Epilogue: + b2, direct stores
    const int colOff = (lane & 3) * 2;
    const int rowOff = lane >> 2;
    #pragma unroll
    for (int mt = 0; mt < 2; ++mt) {
        const int r0 = mBase + warpM * 32 + mt * 16 + rowOff;
        float* row0 = out + (size_t)r0 * ND + nBase + warpN * 64 + colOff;
        float* row1 = row0 + (size_t)8 * ND;
        #pragma unroll
        for (int nt = 0; nt < 8; ++nt) {
            const float bx = __ldg(b2 + nBase + warpN * 64 + nt * 8 + colOff);
            const float by = __ldg(b2 + nBase + warpN * 64 + nt * 8 + colOff + 1);
            *(float2*)(row0 + nt * 8) = make_float2(acc[mt][nt][0] + bx, acc[mt][nt][1] + by);
            *(float2*)(row1 + nt * 8) = make_float2(acc[mt][nt][2] + bx, acc[mt][nt][3] + by);
        }
    }
}

// ---------------------------------------------------------------------------
// Length pass-through tail
// ---------------------------------------------------------------------------
__global__ void tail_kernel(const int* __restrict__ sl, const int* __restrict__ tl,
                            float* __restrict__ out)
{
    const int i = threadIdx.x;
    if (i < NB)           out[MAIN_OUT + i] = (float)sl[i];
    else if (i < 2 * NB)  out[MAIN_OUT + i] = (float)tl[i - NB];
}

extern "C" void kernel_launch(void* const* d_in, const int* in_sizes, int n_in,
                              void* d_out, int out_size)
{
    const float* src  = (const float*)d_in[0];
    const int*   slen = (const int*)  d_in[1];
    const float* tgt  = (const float*)d_in[2];
    const int*   tlen = (const int*)  d_in[3];
    const float* W1   = (const float*)d_in[4];
    const float* b1   = (const float*)d_in[5];
    const float* W2   = (const float*)d_in[6];
    const float* b2   = (const float*)d_in[7];
    float* out = (float*)d_out;

    // Opt-in to >48KB dynamic smem (host-side, capture-safe).
    cudaFuncSetAttribute(stage1_mma_kernel,
                         cudaFuncAttributeMaxDynamicSharedMemorySize, SMEM1);
    cudaFuncSetAttribute(stage2_mma_kernel,
                         cudaFuncAttributeMaxDynamicSharedMemorySize, SMEM2);

    // Fused weight preconverts
    wconv_kernel<<<(W1N + W2N) / 256, 256>>>(W1, W2);

    // Stage 1: P = [S; Tgt] @ W1 (+ b1 on Tgt rows)
    stage1_mma_kernel<<<dim3(NH / 128, P_ROWS / 128), 256, SMEM1>>>(src, tgt, b1);

    // Stage 1.5: H = fp16(tanh.approx(Ps + Pt)), 2x-parallel u-split
    h_kernel<<<PS_ROWS, 256>>>();

    // Stage 2: cp.async-pipelined fp16 GEMM (R13-exact config)
    stage2_mma_kernel<<<dim3(ND / 128, M2 / 128), 256, SMEM2>>>(b2, out);

    // Length pass-through if the output buffer has room
    if ((long)out_size >= MAIN_OUT + 2 * NB)
        tail_kernel<<<1, 32>>>(slen, tlen, out);
}